// round 14
// baseline (speedup 1.0000x reference)
#include <cuda_runtime.h>
#include <math.h>

#define TLEN 8192
#define NTH  1024
#define EPT  8           // elements per thread in prep (NTH*EPT == TLEN)
#define NWARP (NTH/32)   // 32 warps

__device__ float4 g_k4[TLEN / 4];   // final kernel k (with 1/W folded in)

__device__ __forceinline__ float squashf(float v, float lo, float hi) {
    return lo + (hi - lo) / (1.0f + __expf(-v));
}

// ---------------------------------------------------------------------------
// Prep: compute k_t / W entirely in registers + warp shuffles. (~2us, R4 WIN)
// Fires launch_dependents FIRST so gemv CTAs spawn and stream X while this
// kernel computes k.
// ---------------------------------------------------------------------------
__global__ void __launch_bounds__(NTH) prep_kernel(
    const float* fsn, const float* fin, const float* fdn, const float* ftn,
    const float* won, const float* wtn, const void* Fin)
{
    asm volatile("griddepcontrol.launch_dependents;" ::: "memory");

    __shared__ float sWA[NWARP];
    __shared__ float sWB[NWARP];
    __shared__ float sEx[NTH];

    const int tid  = threadIdx.x;
    const int lane = tid & 31;
    const int wid  = tid >> 5;

    // F is an int scalar (44100); guard against float encoding.
    int   Fi = *(const int*)Fin;
    float Ff = *(const float*)Fin;
    float F  = (Fi > 0 && Fi < 100000000) ? (float)Fi : Ff;

    const float f_start = squashf(*fsn, 200.0f, 4000.0f);
    const float f_inf   = squashf(*fin, 20.0f, 500.0f);
    const float f_decay = squashf(*fdn, 0.0f, 2.0f);
    const float f_T     = squashf(*ftn, 0.0f, 2.0f);
    const float w_off   = squashf(*won, 0.0f, 1.0f);
    const float w_T     = squashf(*wtn, 0.01f, 0.5f);

    const float c      = 0.5098245285339035f * F * 0.3183098861837907f;
    const float lbase  = -0.35667494393873245f - f_decay * 2.302585092994046f;
    const float escale = 0.1f * __expf(f_T * 2.302585092994046f);
    const float inv_wT = 1.0f / w_T;
    const float lk     = lbase * escale * (1.0f / (float)TLEN);

    float atau[EPT + 1];
    float wreg[EPT];
    const int tbase = TLEN - 1 - tid * EPT;   // t(0)
    #pragma unroll
    for (int j = 0; j <= EPT; j++) {
        float ti = (float)(tbase + 1 - j);    // tau(j)
        float f  = f_inf + (f_start - f_inf) * __expf(lk * ti);
        atau[j]  = (f - c) / (f + c);
    }
    float wsum = 0.0f;
    #pragma unroll
    for (int j = 0; j < EPT; j++) {
        float t = (float)(tbase - j) * (1.0f / (float)TLEN);
        wreg[j] = 1.0f / (1.0f + __expf(-(t - w_off) * inv_wT));
        wsum += wreg[j];
    }

    const bool first = (tid == 0);             // owns s=0   (t=8191)
    const bool last  = (tid == NTH - 1);       // owns s=8191 (t=0)

    float lreg[EPT];   // lambda2 after scan1, overwritten by lambda1

    // ===================== scan 1 : lambda2 ==============================
    {
        float A = 1.0f, B = 0.0f;
        #pragma unroll
        for (int j = 0; j < EPT; j++) {
            float Ae = (first && j == 0) ? 0.0f : -atau[j];
            float Be = (last  && j == EPT - 1) ? 0.0f : wreg[j];
            B = fmaf(Ae, B, Be);
            A = Ae * A;
        }
        #pragma unroll
        for (int d = 1; d < 32; d <<= 1) {
            float pA = __shfl_up_sync(0xffffffffu, A, d);
            float pB = __shfl_up_sync(0xffffffffu, B, d);
            if (lane >= d) { B = fmaf(A, pB, B); A = A * pA; }
        }
        if (lane == 31) { sWA[wid] = A; sWB[wid] = B; }
        __syncthreads();
        if (wid == 0) {
            float a = sWA[lane], b = sWB[lane];
            #pragma unroll
            for (int d = 1; d < 32; d <<= 1) {
                float pA = __shfl_up_sync(0xffffffffu, a, d);
                float pB = __shfl_up_sync(0xffffffffu, b, d);
                if (lane >= d) { b = fmaf(a, pB, b); a = a * pA; }
            }
            sWA[lane] = a; sWB[lane] = b;
        }
        __syncthreads();
        float eA = __shfl_up_sync(0xffffffffu, A, 1);
        float eB = __shfl_up_sync(0xffffffffu, B, 1);
        if (lane == 0) { eA = 1.0f; eB = 0.0f; }
        float h = (wid > 0) ? fmaf(eA, sWB[wid - 1], eB) : eB;
        #pragma unroll
        for (int j = 0; j < EPT; j++) {
            float Ae = (first && j == 0) ? 0.0f : -atau[j];
            float Be = (last  && j == EPT - 1) ? 0.0f : wreg[j];
            h = fmaf(Ae, h, Be);
            lreg[j] = h;
        }
    }

    sEx[tid] = lreg[EPT - 1];
    __syncthreads();
    float prevL2 = (tid > 0) ? sEx[tid - 1] : 0.0f;
    __syncthreads();

    // ===================== scan 2 : lambda1 ==============================
    float l2_last = lreg[EPT - 1];
    {
        float A = 1.0f, B = 0.0f;
        #pragma unroll
        for (int j = 0; j < EPT; j++) {
            float bt  = 0.5f * (atau[j + 1] + 1.0f);
            float bt1 = 0.5f * (atau[j] + 1.0f);
            float l2c = lreg[j];
            float l2p = (j == 0) ? prevL2 : lreg[j - 1];
            float Be;
            if (first && j == 0)            Be = bt * l2c;
            else if (last && j == EPT - 1)  Be = bt1 * l2p;
            else                            Be = fmaf(bt, l2c, bt1 * l2p);
            float Ae = (first && j == 0) ? 0.0f : -atau[j];
            B = fmaf(Ae, B, Be);
            A = Ae * A;
        }
        #pragma unroll
        for (int d = 1; d < 32; d <<= 1) {
            float pA = __shfl_up_sync(0xffffffffu, A, d);
            float pB = __shfl_up_sync(0xffffffffu, B, d);
            if (lane >= d) { B = fmaf(A, pB, B); A = A * pA; }
        }
        if (lane == 31) { sWA[wid] = A; sWB[wid] = B; }
        __syncthreads();
        if (wid == 0) {
            float a = sWA[lane], b = sWB[lane];
            #pragma unroll
            for (int d = 1; d < 32; d <<= 1) {
                float pA = __shfl_up_sync(0xffffffffu, a, d);
                float pB = __shfl_up_sync(0xffffffffu, b, d);
                if (lane >= d) { b = fmaf(a, pB, b); a = a * pA; }
            }
            sWA[lane] = a; sWB[lane] = b;
        }
        __syncthreads();
        float eA = __shfl_up_sync(0xffffffffu, A, 1);
        float eB = __shfl_up_sync(0xffffffffu, B, 1);
        if (lane == 0) { eA = 1.0f; eB = 0.0f; }
        float h = (wid > 0) ? fmaf(eA, sWB[wid - 1], eB) : eB;
        float l2p = prevL2;
        #pragma unroll
        for (int j = 0; j < EPT; j++) {
            float bt  = 0.5f * (atau[j + 1] + 1.0f);
            float bt1 = 0.5f * (atau[j] + 1.0f);
            float l2c = lreg[j];
            float Be;
            if (first && j == 0)            Be = bt * l2c;
            else if (last && j == EPT - 1)  Be = bt1 * l2p;
            else                            Be = fmaf(bt, l2c, bt1 * l2p);
            float Ae = (first && j == 0) ? 0.0f : -atau[j];
            h = fmaf(Ae, h, Be);
            lreg[j] = h;                    // l1
            l2p = l2c;
        }
    }

    __syncthreads();
    sEx[tid] = lreg[EPT - 1];
    __syncthreads();
    float prevL1 = (tid > 0) ? sEx[tid - 1] : 0.0f;

    // ===================== W = sum(w) ====================================
    #pragma unroll
    for (int d = 16; d > 0; d >>= 1)
        wsum += __shfl_down_sync(0xffffffffu, wsum, d);
    __syncthreads();
    if (lane == 0) sWA[wid] = wsum;
    __syncthreads();
    if (tid == 0) {
        float s = 0.0f;
        #pragma unroll
        for (int i = 0; i < NWARP; i++) s += sWA[i];
        sWB[0] = 1.0f / s;
    }
    __syncthreads();
    const float invW = sWB[0];

    // ===================== emit k ========================================
    float* kf = (float*)g_k4;
    #pragma unroll
    for (int j = 0; j < EPT; j++) {
        float bt  = 0.5f * (atau[j + 1] + 1.0f);
        float bt1 = 0.5f * (atau[j] + 1.0f);
        float l1c = lreg[j];
        float l1p = (j == 0) ? prevL1 : lreg[j - 1];
        float kv;
        if (first && j == 0) {
            kv = bt * l1c;
        } else if (last && j == EPT - 1) {
            kv = wreg[EPT - 1] + fmaf(bt1, lreg[EPT - 2], l1c + l2_last);
        } else {
            kv = fmaf(bt, l1c, bt1 * l1p);
        }
        kf[tbase - j] = kv * invW;
    }
}

// ---------------------------------------------------------------------------
// GEMV: one row per CTA, 256 threads, 8+8 batched float4 loads (R13 shape,
// best-bucket). X loads issue BEFORE griddepcontrol.wait so they overlap
// prep's compute; k loads come after the wait.
// ---------------------------------------------------------------------------
__global__ void __launch_bounds__(256) gemv_kernel(
    const float* __restrict__ X, float* __restrict__ out)
{
    const int row = blockIdx.x;
    const int tid = threadIdx.x;
    const float4* __restrict__ xr = (const float4*)(X + (size_t)row * TLEN);

    float4 x[8];
    #pragma unroll
    for (int i = 0; i < 8; i++)
        x[i] = xr[i * 256 + tid];            // no k dependency -> overlaps prep

    // Block until prep's writes to g_k4 are visible.
    asm volatile("griddepcontrol.wait;" ::: "memory");

    float4 k[8];
    #pragma unroll
    for (int i = 0; i < 8; i++)
        k[i] = g_k4[i * 256 + tid];

    float a0 = 0.0f, a1 = 0.0f, a2 = 0.0f, a3 = 0.0f;
    #pragma unroll
    for (int i = 0; i < 8; i++) {
        a0 = fmaf(x[i].x, k[i].x, a0);
        a1 = fmaf(x[i].y, k[i].y, a1);
        a2 = fmaf(x[i].z, k[i].z, a2);
        a3 = fmaf(x[i].w, k[i].w, a3);
    }
    float acc = (a0 + a1) + (a2 + a3);

    // warp reduce
    #pragma unroll
    for (int off = 16; off > 0; off >>= 1)
        acc += __shfl_down_sync(0xffffffffu, acc, off);

    __shared__ float sred[8];
    int w = tid >> 5, l = tid & 31;
    if (l == 0) sred[w] = acc;
    __syncthreads();
    if (tid == 0) {
        float s = 0.0f;
        #pragma unroll
        for (int i = 0; i < 8; i++) s += sred[i];
        out[row] = s;
    }
}

extern "C" void kernel_launch(void* const* d_in, const int* in_sizes, int n_in,
                              void* d_out, int out_size)
{
    const float* X = (const float*)d_in[0];
    const void*  F = d_in[1];

    prep_kernel<<<1, NTH>>>(
        (const float*)d_in[2], (const float*)d_in[3], (const float*)d_in[4],
        (const float*)d_in[5], (const float*)d_in[6], (const float*)d_in[7], F);

    int rows = in_sizes[0] / TLEN;

    // PDL: gemv spawns as soon as prep fires launch_dependents (its first
    // instruction); the in-kernel griddepcontrol.wait guards the g_k4 reads.
    cudaLaunchConfig_t cfg = {};
    cfg.gridDim  = dim3(rows, 1, 1);
    cfg.blockDim = dim3(256, 1, 1);
    cfg.dynamicSmemBytes = 0;
    cfg.stream = 0;
    cudaLaunchAttribute attrs[1];
    attrs[0].id = cudaLaunchAttributeProgrammaticStreamSerialization;
    attrs[0].val.programmaticStreamSerializationAllowed = 1;
    cfg.attrs = attrs;
    cfg.numAttrs = 1;
    cudaLaunchKernelEx(&cfg, gemv_kernel, X, (float*)d_out);
}